// round 9
// baseline (speedup 1.0000x reference)
#include <cuda_runtime.h>
#include <math.h>
#include <stdint.h>

#define H       16
#define DM      1024
#define DK      64
#define NW      16384
#define NCHUNK  256     // w-pass chunks; 64 rows each

typedef unsigned long long u64;

// ---- scratch (static __device__ arrays; no allocation) ----
__device__ __align__(16) float g_q[DM];
__device__ __align__(16) float g_a[H * DM];
__device__ __align__(16) float g_c[H];
__device__ __align__(16) float g_p[H * NW];       // unnormalized p = exp(score)
__device__ __align__(16) float g_Zpart[H * 512];  // per-scores-block exp-sum partials
__device__ __align__(16) float g_wpart[NCHUNK][H * DM];
__device__ __align__(16) float g_w[H * DM];
__device__ __align__(16) float g_x[DM];

__device__ __forceinline__ float warp_red(float v) {
#pragma unroll
    for (int o = 16; o; o >>= 1) v += __shfl_down_sync(0xffffffffu, v, o);
    return v;
}

// packed f32x2 FMA (Blackwell)
__device__ __forceinline__ u64 fma2(u64 a, u64 b, u64 c) {
    u64 d;
    asm("fma.rn.f32x2 %0, %1, %2, %3;" : "=l"(d) : "l"(a), "l"(b), "l"(c));
    return d;
}
__device__ __forceinline__ float sum2(u64 v) {
    return __uint_as_float((unsigned)v) + __uint_as_float((unsigned)(v >> 32));
}

// cp.async helpers
__device__ __forceinline__ void cp_async16(uint32_t smem_addr, const void* gptr) {
    asm volatile("cp.async.cg.shared.global [%0], [%1], 16;"
                 :: "r"(smem_addr), "l"(gptr));
}
#define CP_COMMIT()  asm volatile("cp.async.commit_group;")
#define CP_WAIT(n)   asm volatile("cp.async.wait_group %0;" :: "n"(n))

// ---- k_scores SMEM (floats): 3-stage, 64-j tiles ----
// kt stage: 32 rows x 68 (64 j + pad) = 2176 fl; at stage: 16 x 68 = 1088 fl
#define SCC_KT(s)  ((s) * 2176)
#define SCC_AT(s)  (6528 + (s) * 1088)
#define SCC_FLOATS 9792
#define SCC_BYTES  (SCC_FLOATS * 4)     // 39168

// ---- k_wpass SMEM: 3-stage x 4-row value tiles + p2 ----
#define WPV(s)     ((s) * 4096)         // 4 rows x 1024 floats per stage
#define WP_P2      12288                // u64[1024] after the 3 stages
#define WP_BYTES   (12288 * 4 + 1024 * 8)   // 57344

// ------------------------------------------------------------------
// 1) q[i] = dot(query, Wq[i]) + bq[i].  grid 128 x 256 (warp per row)
// ------------------------------------------------------------------
__global__ void k_qproj(const float* __restrict__ query,
                        const float* __restrict__ Wq,
                        const float* __restrict__ bq) {
    __shared__ __align__(16) float qs[DM];
    const int tid = threadIdx.x;
    for (int i = tid; i < DM; i += 256) qs[i] = query[i];
    __syncthreads();
    const int w = tid >> 5, lane = tid & 31;
    const int row = blockIdx.x * 8 + w;
    const float4* wr = (const float4*)(Wq + (size_t)row * DM);
    const float4* q4 = (const float4*)qs;
    float acc = 0.f;
#pragma unroll 8
    for (int k = lane; k < DM / 4; k += 32) {
        float4 a = wr[k], b = q4[k];
        acc += a.x * b.x + a.y * b.y + a.z * b.z + a.w * b.w;
    }
    acc = warp_red(acc);
    if (lane == 0) g_q[row] = acc + bq[row];
}

// ------------------------------------------------------------------
// 2) a[h][j] = sum_d q[h*64+d]*Wk[h*64+d][j];  c[h] = sum_d q*bk
//    grid 64 x 128, two launches (hofs 0/8) so k_scores is ncu idx 3.
// ------------------------------------------------------------------
__global__ void k_aprep(const float* __restrict__ Wk,
                        const float* __restrict__ bk, int hofs) {
    const int h = hofs + (blockIdx.x >> 3), sl = blockIdx.x & 7;
    const int tid = threadIdx.x;
    __shared__ float qh[DK];
    if (tid < DK) qh[tid] = g_q[h * DK + tid];
    __syncthreads();
    const int j = sl * 128 + tid;
    const float* base = Wk + (size_t)(h * DK) * DM + j;
    float acc = 0.f;
#pragma unroll 8
    for (int d = 0; d < DK; d++) acc += qh[d] * base[(size_t)d * DM];
    g_a[h * DM + j] = acc;
    if (sl == 0 && tid < 32) {
        float c = 0.f;
        for (int d = tid; d < DK; d += 32) c += qh[d] * bk[h * DK + d];
        c = warp_red(c);
        if (tid == 0) g_c[h] = c;
    }
}

// ------------------------------------------------------------------
// 3) k_scores: p[h][n] = exp(dot(key[n], a[h]) + c[h]), Z partials.
//    grid 512 x 256, 3 blocks/SM (24 warps). 32 rows/block.
//    16 tiles of 64 j; 3-stage cp.async pipeline (key + a per stage);
//    ONE barrier per tile. Warp = 8-j slice; acc = 16 x u64 (32 regs).
// ------------------------------------------------------------------
__global__ void __launch_bounds__(256, 3) k_scores(const float* __restrict__ key) {
    extern __shared__ __align__(16) float smem[];
    const int tid = threadIdx.x;
    const int w = tid >> 5, lane = tid & 31;
    const int n0 = blockIdx.x * 32;

    const uint32_t smem_u32 = (uint32_t)__cvta_generic_to_shared(smem);

    // staging maps
    const int kr  = tid >> 3;            // key row 0..31
    const int kc0 = (tid & 7) * 2;       // key f4 col base (2 per thread)
    const int ar  = tid >> 4;            // a head 0..15
    const int ac  = tid & 15;            // a f4 col

    const float* krow = key + (size_t)(n0 + kr) * DM;
    const float4* ga4 = (const float4*)g_a;

#define SC_ISSUE(st, tt)                                                        \
    do {                                                                        \
        const uint32_t dk = smem_u32 + SCC_KT(st) * 4;                          \
        const uint32_t da = smem_u32 + SCC_AT(st) * 4;                          \
        cp_async16(dk + (kr * 68 + kc0 * 4) * 4,       krow + (tt) * 64 + kc0 * 4);     \
        cp_async16(dk + (kr * 68 + (kc0 + 1) * 4) * 4, krow + (tt) * 64 + (kc0 + 1) * 4);\
        cp_async16(da + (ar * 68 + ac * 4) * 4,  ga4 + ar * 256 + (tt) * 16 + ac);      \
        CP_COMMIT();                                                            \
    } while (0)

    SC_ISSUE(0, 0);
    SC_ISSUE(1, 1);

    u64 acc[16];
#pragma unroll
    for (int h = 0; h < 16; h++) acc[h] = 0ull;

#pragma unroll
    for (int t = 0; t < 16; t++) {
        if (t == 15) { CP_WAIT(0); } else { CP_WAIT(1); }
        __syncthreads();
        const int s = t % 3;
        const float* ktb = smem + SCC_KT(s);
        const float* atb = smem + SCC_AT(s);
#pragma unroll
        for (int q = 0; q < 2; q++) {
            const int j = w * 8 + q * 4;
            const ulonglong2 kv = *(const ulonglong2*)&ktb[lane * 68 + j];
#pragma unroll
            for (int h = 0; h < 16; h++) {
                const ulonglong2 av = *(const ulonglong2*)&atb[h * 68 + j];
                acc[h] = fma2(kv.x, av.x, acc[h]);
                acc[h] = fma2(kv.y, av.y, acc[h]);
            }
        }
        if (t < 14) {
            const int sn = (t + 2) % 3;
            SC_ISSUE(sn, t + 2);
        }
    }
#undef SC_ISSUE

    // cross-warp reduction; kt0/kt1 region (4352 fl >= 4096) as scratch
    __syncthreads();
    float* red = smem;
#pragma unroll
    for (int h = 0; h < 16; h++)
        red[h * 256 + w * 32 + lane] = sum2(acc[h]);
    __syncthreads();
    const int h0 = tid >> 5;
    const int r  = tid & 31;
#pragma unroll
    for (int s = 0; s < 2; s++) {
        const int hh = h0 + 8 * s;
        float v = g_c[hh];
#pragma unroll
        for (int ww = 0; ww < 8; ww++) v += red[hh * 256 + ww * 32 + r];
        const float e = __expf(v);
        g_p[hh * NW + n0 + r] = e;
        float z = warp_red(e);
        if (r == 0) g_Zpart[hh * 512 + blockIdx.x] = z;
    }
}

// ------------------------------------------------------------------
// 4) k_wpass: wpart[c][h][j] = sum_{n in chunk} p[h][n]*value[n][j].
//    grid 256 x 256 (2/SM). 64 rows/chunk; 16 stages of 4 rows,
//    3-stage cp.async pipeline. Inner loop = pure LDS + FFMA2.
// ------------------------------------------------------------------
__global__ void __launch_bounds__(256, 2) k_wpass(const float* __restrict__ value) {
    extern __shared__ __align__(16) float smem[];
    u64* p2 = (u64*)(smem + WP_P2);
    const int tid = threadIdx.x;
    const int n0 = blockIdx.x * 64;

    const uint32_t smem_u32 = (uint32_t)__cvta_generic_to_shared(smem);
    const float4* val4 = (const float4*)value;

#define WP_ISSUE(st, tt)                                                        \
    do {                                                                        \
        const uint32_t dv = smem_u32 + WPV(st) * 4;                             \
        _Pragma("unroll")                                                       \
        for (int k = 0; k < 4; k++) {                                           \
            const int f = k * 256 + tid;                                        \
            cp_async16(dv + f * 16, val4 + (size_t)(n0 + (tt) * 4) * 256 + f);  \
        }                                                                       \
        CP_COMMIT();                                                            \
    } while (0)

    WP_ISSUE(0, 0);
    WP_ISSUE(1, 1);

    // p tile: load + dup-pack (overlaps with cp.async in flight)
    for (int i = tid; i < H * 64; i += 256) {
        const int h = i >> 6, n = i & 63;
        const unsigned b = __float_as_uint(g_p[h * NW + n0 + n]);
        p2[i] = ((u64)b << 32) | b;
    }

    ulonglong2 acc[H];
#pragma unroll
    for (int h = 0; h < H; h++) acc[h] = make_ulonglong2(0ull, 0ull);

#pragma unroll
    for (int t = 0; t < 16; t++) {
        if (t == 15) { CP_WAIT(0); } else { CP_WAIT(1); }
        __syncthreads();   // also covers initial p2 visibility at t=0
        const ulonglong2* vs = (const ulonglong2*)(smem + WPV(t % 3));
        const ulonglong2 v0 = vs[0 * 256 + tid];
        const ulonglong2 v1 = vs[1 * 256 + tid];
        const ulonglong2 v2 = vs[2 * 256 + tid];
        const ulonglong2 v3 = vs[3 * 256 + tid];
#pragma unroll
        for (int h = 0; h < H; h++) {
            const u64* ph = &p2[h * 64 + t * 4];
            const ulonglong2 pA = *(const ulonglong2*)(ph + 0);   // rows 0,1
            const ulonglong2 pB = *(const ulonglong2*)(ph + 2);   // rows 2,3
            acc[h].x = fma2(pA.x, v0.x, acc[h].x); acc[h].y = fma2(pA.x, v0.y, acc[h].y);
            acc[h].x = fma2(pA.y, v1.x, acc[h].x); acc[h].y = fma2(pA.y, v1.y, acc[h].y);
            acc[h].x = fma2(pB.x, v2.x, acc[h].x); acc[h].y = fma2(pB.x, v2.y, acc[h].y);
            acc[h].x = fma2(pB.y, v3.x, acc[h].x); acc[h].y = fma2(pB.y, v3.y, acc[h].y);
        }
        if (t < 14) WP_ISSUE((t + 2) % 3, t + 2);
    }
#undef WP_ISSUE

    ulonglong2* wp = (ulonglong2*)&g_wpart[blockIdx.x][0];
#pragma unroll
    for (int h = 0; h < H; h++) wp[h * 256 + tid] = acc[h];
}

// ------------------------------------------------------------------
// 5) w[i] = (sum_c wpart[c][i]) / Z[h].  grid 256 x 256.
// ------------------------------------------------------------------
__global__ void k_wreduce() {
    __shared__ __align__(16) float4 part[256];
    __shared__ float zs;
    const int tid = threadIdx.x;
    const int cseg = tid >> 4;
    const int col  = tid & 15;
    const int b = blockIdx.x;
    const int h = b >> 4;
    const int f4col = b * 16 + col;

    const float4* wp4 = (const float4*)&g_wpart[0][0];
    float4 acc = make_float4(0.f, 0.f, 0.f, 0.f);
#pragma unroll
    for (int k = 0; k < 16; k++) {
        const float4 v = wp4[(size_t)(cseg * 16 + k) * 4096 + f4col];
        acc.x += v.x; acc.y += v.y; acc.z += v.z; acc.w += v.w;
    }
    part[tid] = acc;

    if (tid < 32) {
        const float4* zp = (const float4*)(g_Zpart + h * 512);
        float z = 0.f;
#pragma unroll
        for (int k = 0; k < 4; k++) {
            const float4 v = zp[tid * 4 + k];
            z += v.x + v.y + v.z + v.w;
        }
        z = warp_red(z);
        if (tid == 0) zs = z;
    }
    __syncthreads();

    if (tid < 16) {
        float4 s = part[tid];
#pragma unroll
        for (int k = 1; k < 16; k++) {
            const float4 v = part[k * 16 + tid];
            s.x += v.x; s.y += v.y; s.z += v.z; s.w += v.w;
        }
        const float inv = 1.0f / zs;
        s.x *= inv; s.y *= inv; s.z *= inv; s.w *= inv;
        ((float4*)g_w)[b * 16 + tid] = s;
    }
}

// ------------------------------------------------------------------
// 6) x[i] = dot(w[h], Wv[i]) + bv[i], h = i/64.  grid 128 x 256.
// ------------------------------------------------------------------
__global__ void k_xproj(const float* __restrict__ Wv,
                        const float* __restrict__ bv) {
    __shared__ __align__(16) float ws[DM];
    const int tid = threadIdx.x;
    const int h = blockIdx.x >> 3;
    for (int i = tid; i < DM; i += 256) ws[i] = g_w[h * DM + i];
    __syncthreads();
    const int w = tid >> 5, lane = tid & 31;
    const int row = blockIdx.x * 8 + w;
    const float4* wr = (const float4*)(Wv + (size_t)row * DM);
    const float4* q4 = (const float4*)ws;
    float acc = 0.f;
#pragma unroll 8
    for (int k = lane; k < DM / 4; k += 32) {
        float4 a = wr[k], b = q4[k];
        acc += a.x * b.x + a.y * b.y + a.z * b.z + a.w * b.w;
    }
    acc = warp_red(acc);
    if (lane == 0) g_x[row] = acc + bv[row];
}

// ------------------------------------------------------------------
// 7) out[i] = dot(x, Wo[i]) + bo[i].  grid 128 x 256.
// ------------------------------------------------------------------
__global__ void k_out(const float* __restrict__ Wo,
                      const float* __restrict__ bo,
                      float* __restrict__ out) {
    __shared__ __align__(16) float xs[DM];
    const int tid = threadIdx.x;
    for (int i = tid; i < DM; i += 256) xs[i] = g_x[i];
    __syncthreads();
    const int w = tid >> 5, lane = tid & 31;
    const int row = blockIdx.x * 8 + w;
    const float4* wr = (const float4*)(Wo + (size_t)row * DM);
    const float4* q4 = (const float4*)xs;
    float acc = 0.f;
#pragma unroll 8
    for (int k = lane; k < DM / 4; k += 32) {
        float4 a = wr[k], b = q4[k];
        acc += a.x * b.x + a.y * b.y + a.z * b.z + a.w * b.w;
    }
    acc = warp_red(acc);
    if (lane == 0) out[row] = acc + bo[row];
}

// ------------------------------------------------------------------
extern "C" void kernel_launch(void* const* d_in, const int* in_sizes, int n_in,
                              void* d_out, int out_size) {
    (void)in_sizes; (void)n_in; (void)out_size;
    const float* query = (const float*)d_in[0];
    const float* key   = (const float*)d_in[1];
    const float* value = (const float*)d_in[2];
    const float* Wq    = (const float*)d_in[3];
    const float* bq    = (const float*)d_in[4];
    const float* Wk    = (const float*)d_in[5];
    const float* bk    = (const float*)d_in[6];
    const float* Wv    = (const float*)d_in[7];
    const float* bv    = (const float*)d_in[8];
    const float* Wo    = (const float*)d_in[9];
    const float* bo    = (const float*)d_in[10];
    float* out = (float*)d_out;

    cudaFuncSetAttribute(k_scores, cudaFuncAttributeMaxDynamicSharedMemorySize,
                         SCC_BYTES);
    cudaFuncSetAttribute(k_wpass, cudaFuncAttributeMaxDynamicSharedMemorySize,
                         WP_BYTES);

    k_qproj  <<<128, 256>>>(query, Wq, bq);          // idx 0
    k_aprep  <<<64, 128>>>(Wk, bk, 0);               // idx 1
    k_aprep  <<<64, 128>>>(Wk, bk, 8);               // idx 2
    k_scores <<<512, 256, SCC_BYTES>>>(key);         // idx 3  <- ncu window
    k_wpass  <<<NCHUNK, 256, WP_BYTES>>>(value);     // idx 4
    k_wreduce<<<256, 256>>>();                       // idx 5
    k_xproj  <<<128, 256>>>(Wv, bv);                 // idx 6
    k_out    <<<128, 256>>>(Wo, bo, out);            // idx 7
}